// round 10
// baseline (speedup 1.0000x reference)
#include <cuda_runtime.h>
#include <cstddef>
#include <cstdint>

#define NPTS 1000000
#define KSZ 9
#define EPSBN 1e-5f
#define NF4 (NPTS * 16 / 4)
#define TILES_PER_BLOCK 5
#define CONVGRID 3125             // 3125 blocks * 5 tiles * 64 pts = 1M exact
#define MIDB 64
#define RPB ((CONVGRID + MIDB - 1) / MIDB)   // 49
#define SGRID 1184
#define SSTRIDE (SGRID * 256)
#define TILE_F4 2304              // 4u * 9j * 64p float4 per buffer
#define CONV_SMEM (2 * TILE_F4 * 16 + KSZ * 256 * 4)   // 73728 + 9216 = 82944

typedef unsigned long long ull;

// ---------------- scratch (device globals: no allocation) ----------------
__device__ float g_h[(size_t)NPTS * 16];           // conv1 raw output, 64 MB
__device__ float4 g_part4[CONVGRID * 8];           // per-block stats partials
__device__ float g_mid[MIDB * 32];
__device__ __align__(16) float g_st1[32];          // BN1 scale[16], shift[16]
__device__ __align__(16) float g_st2[32];          // BN2 scale[16], shift[16]

// ---------------- f32x2 packed helpers ----------------
__device__ __forceinline__ void unpack2(ull v, float& lo, float& hi) {
    asm("mov.b64 {%0, %1}, %2;" : "=f"(lo), "=f"(hi) : "l"(v));
}
__device__ __forceinline__ ull pack2(float lo, float hi) {
    ull r; asm("mov.b64 %0, {%1, %2};" : "=l"(r) : "f"(lo), "f"(hi)); return r;
}
__device__ __forceinline__ ull fma2(ull a, ull b, ull c) {
    ull d; asm("fma.rn.f32x2 %0, %1, %2, %3;" : "=l"(d) : "l"(a), "l"(b), "l"(c)); return d;
}

// =====================================================================
// Tree-conv: double-buffered cp.async pipeline over 5 tiles of 64 points.
//  stage(t+1) -> wait_group 1 -> compute(t): gather latency hidden in-CTA.
//  Compute: thread = (q = o-quarter, grp); 2 points; per (j,c) one
//  LDS.128 weight read (4 addrs/warp, conflict-free) + 4 fma2.
//  Stats accumulated in registers across tiles; one smem reduce at end.
// =====================================================================
template <bool BIAS>
__global__ void __launch_bounds__(128) conv_kernel(
    const float* __restrict__ src, const int* __restrict__ ind,
    const float* __restrict__ w, const float* __restrict__ bias,
    float* __restrict__ dst)
{
    extern __shared__ __align__(16) unsigned char dynsmem[];
    float4* sdat = reinterpret_cast<float4*>(dynsmem);                  // 2 * 2304
    float*  wsm  = reinterpret_cast<float*>(dynsmem + 2 * TILE_F4 * 16); // 2304 floats

    const int tid = threadIdx.x;
    const int q = tid & 3;
    const int grp = tid >> 2;            // 0..31

    // ---- stage weights: w[c][o][j] -> wsm[j][c][o] ----
    for (int i = tid; i < 16 * 16 * KSZ; i += 128) {
        int c = i / 144;
        int rem = i - c * 144;
        int o = rem / 9;
        int j = rem - o * 9;
        wsm[(j * 16 + c) * 16 + o] = w[i];
    }

    const float4* sp = reinterpret_cast<const float4*>(src);
    const int tile0 = blockIdx.x * TILES_PER_BLOCK;

    // stage one 64-point tile into buffer buf
    auto stage = [&](int tile, int buf) {
        const int base9 = tile * 576;              // ind offset of tile (64 pts * 9)
        float4* sb = sdat + buf * TILE_F4;
#pragma unroll
        for (int t = 0; t < 18; t++) {
            int i = tid + 128 * t;                 // 0..2303
            int u = i & 3;
            int jp = i >> 2;                       // 0..575 == p*9 + j
            int row = __ldg(ind + base9 + jp);     // consecutive -> coalesced
            int p = jp / 9;
            int j = jp - p * 9;
            const float4* gsrc = sp + (size_t)row * 4 + u;
            uint32_t sa = (uint32_t)__cvta_generic_to_shared(&sb[(u * 9 + j) * 64 + p]);
            asm volatile("cp.async.cg.shared.global [%0], [%1], 16;"
                         :: "r"(sa), "l"(gsrc));
        }
        asm volatile("cp.async.commit_group;");
    };

    float4 b4 = make_float4(0.f, 0.f, 0.f, 0.f);
    if (BIAS) b4 = reinterpret_cast<const float4*>(bias)[q];
    float4 s4 = make_float4(0.f, 0.f, 0.f, 0.f);
    float4 q4 = make_float4(0.f, 0.f, 0.f, 0.f);

    stage(tile0, 0);

    for (int t = 0; t < TILES_PER_BLOCK; t++) {
        if (t + 1 < TILES_PER_BLOCK) {
            stage(tile0 + t + 1, (t + 1) & 1);
            asm volatile("cp.async.wait_group 1;" ::: "memory");
        } else {
            asm volatile("cp.async.wait_group 0;" ::: "memory");
        }
        __syncthreads();   // staged data (and, on t==0, weights) visible

        const float4* sb = sdat + (t & 1) * TILE_F4;
        ull a0x = 0, a0y = 0, a1x = 0, a1y = 0;

        for (int j = 0; j < KSZ; j++) {
            float4 A0[4], A1[4];
#pragma unroll
            for (int u = 0; u < 4; u++) {
                A0[u] = sb[(u * KSZ + j) * 64 + grp];
                A1[u] = sb[(u * KSZ + j) * 64 + grp + 32];
            }
            const float* wj = wsm + j * 256;
#pragma unroll
            for (int c = 0; c < 16; c++) {
                const float v0 = (&A0[c >> 2].x)[c & 3];
                const float v1 = (&A1[c >> 2].x)[c & 3];
                ulonglong2 ww = *reinterpret_cast<const ulonglong2*>(wj + c * 16 + q * 4);
                const ull v0p = pack2(v0, v0);
                const ull v1p = pack2(v1, v1);
                a0x = fma2(v0p, ww.x, a0x);
                a0y = fma2(v0p, ww.y, a0y);
                a1x = fma2(v1p, ww.x, a1x);
                a1y = fma2(v1p, ww.y, a1y);
            }
        }

        float o0[2], o1[2], o2[2], o3[2];
        unpack2(a0x, o0[0], o1[0]); unpack2(a0y, o2[0], o3[0]);
        unpack2(a1x, o0[1], o1[1]); unpack2(a1y, o2[1], o3[1]);
#pragma unroll
        for (int k = 0; k < 2; k++) {
            if (BIAS) {
                o0[k] += b4.x; o1[k] += b4.y; o2[k] += b4.z; o3[k] += b4.w;
            }
            const int p = (tile0 + t) * 64 + grp + 32 * k;
            reinterpret_cast<float4*>(dst)[(size_t)p * 4 + q] =
                make_float4(o0[k], o1[k], o2[k], o3[k]);
            s4.x += o0[k]; s4.y += o1[k]; s4.z += o2[k]; s4.w += o3[k];
            q4.x += o0[k] * o0[k]; q4.y += o1[k] * o1[k];
            q4.z += o2[k] * o2[k]; q4.w += o3[k] * o3[k];
        }
        __syncthreads();   // buffer free before next stage overwrites it
    }

    // ---- per-block stats reduce (reuse wsm region; deterministic) ----
    float4* s1 = reinterpret_cast<float4*>(wsm);       // 128 float4 = 2KB
    float4* s2 = s1 + 128;                             // 2KB (wsm has 9KB)
    s1[tid] = s4; s2[tid] = q4;
    __syncthreads();
#pragma unroll
    for (int off = 64; off >= 4; off >>= 1) {
        if (tid < off) {
            float4 a = s1[tid], b = s1[tid + off];
            a.x += b.x; a.y += b.y; a.z += b.z; a.w += b.w; s1[tid] = a;
            float4 c = s2[tid], d = s2[tid + off];
            c.x += d.x; c.y += d.y; c.z += d.z; c.w += d.w; s2[tid] = c;
        }
        __syncthreads();
    }
    if (tid < 4) {
        g_part4[blockIdx.x * 8 + tid] = s1[tid];       // sums, channel group tid
        g_part4[blockIdx.x * 8 + 4 + tid] = s2[tid];   // squares
    }
}

// ---------------- BN1 + leaky applied in place on g_h ----------------
__global__ __launch_bounds__(256) void bnapply_kernel()
{
    const int tid = threadIdx.x;
    const int idx = blockIdx.x * 256 + tid;
    const int g = tid & 3;
    float4 sc = reinterpret_cast<const float4*>(g_st1)[g];
    float4 sh = reinterpret_cast<const float4*>(g_st1 + 16)[g];
    float4* hh = reinterpret_cast<float4*>(g_h);
    for (int i = idx; i < NF4; i += SSTRIDE) {
        float4 v = hh[i];
        v.x = fmaf(v.x, sc.x, sh.x); v.x = fmaxf(v.x, 0.2f * v.x);
        v.y = fmaf(v.y, sc.y, sh.y); v.y = fmaxf(v.y, 0.2f * v.y);
        v.z = fmaf(v.z, sc.z, sh.z); v.z = fmaxf(v.z, 0.2f * v.z);
        v.w = fmaf(v.w, sc.w, sh.w); v.w = fmaxf(v.w, 0.2f * v.w);
        hh[i] = v;
    }
}

// ---------------- mid-stage stats reduction: CONVGRID -> 64 partials ----------------
__global__ __launch_bounds__(256) void midstats_kernel()
{
    const float* part = reinterpret_cast<const float*>(g_part4);
    const int tid = threadIdx.x;
    const int v = tid & 31;
    const int lane = tid >> 5;
    const int r0 = blockIdx.x * RPB;
    const int rend = min(r0 + RPB, CONVGRID);
    float loc = 0.f;
    for (int r = r0 + lane; r < rend; r += 8) loc += part[r * 32 + v];
    __shared__ float sm[256];
    sm[tid] = loc;
    __syncthreads();
    if (tid < 32) {
        float t = 0.f;
#pragma unroll
        for (int k = 0; k < 8; k++) t += sm[tid + k * 32];
        g_mid[blockIdx.x * 32 + tid] = t;
    }
}

// ---------------- finalize: 64 partials -> BN scale/shift ----------------
template <int S>
__global__ void finalize_kernel(const float* __restrict__ gamma,
                                const float* __restrict__ beta)
{
    const int tid = threadIdx.x;   // 32 threads
    __shared__ float sm[32];
    float t = 0.f;
    for (int r = 0; r < MIDB; r++) t += g_mid[r * 32 + tid];
    sm[tid] = t;
    __syncthreads();
    if (tid < 16) {
        const float inv_n = 1.0f / (float)NPTS;
        float mean = sm[tid] * inv_n;
        float var = sm[16 + tid] * inv_n - mean * mean;
        float rstd = rsqrtf(var + EPSBN);
        float sc = gamma[tid] * rstd;
        float sh = beta[tid] - mean * sc;
        float* st = (S == 1) ? g_st1 : g_st2;
        st[tid] = sc;
        st[16 + tid] = sh;
    }
}

// ---------- epilogue: out = leaky(BN2(raw2) + data), in place on d_out ----------
__global__ __launch_bounds__(256) void bnres_kernel(
    const float* __restrict__ data, float* __restrict__ out)
{
    const int tid = threadIdx.x;
    const int idx = blockIdx.x * 256 + tid;
    const int g = tid & 3;
    float4 sc = reinterpret_cast<const float4*>(g_st2)[g];
    float4 sh = reinterpret_cast<const float4*>(g_st2 + 16)[g];
    const float4* dd = reinterpret_cast<const float4*>(data);
    float4* oo = reinterpret_cast<float4*>(out);
    for (int i = idx; i < NF4; i += SSTRIDE) {
        float4 r = oo[i];
        float4 d = dd[i];
        float4 y;
        y.x = fmaf(r.x, sc.x, sh.x) + d.x;
        y.y = fmaf(r.y, sc.y, sh.y) + d.y;
        y.z = fmaf(r.z, sc.z, sh.z) + d.z;
        y.w = fmaf(r.w, sc.w, sh.w) + d.w;
        y.x = fmaxf(y.x, 0.2f * y.x);
        y.y = fmaxf(y.y, 0.2f * y.y);
        y.z = fmaxf(y.z, 0.2f * y.z);
        y.w = fmaxf(y.w, 0.2f * y.w);
        oo[i] = y;
    }
}

extern "C" void kernel_launch(void* const* d_in, const int* in_sizes, int n_in,
                              void* d_out, int out_size)
{
    const float* data   = (const float*)d_in[0];
    const int*   ind    = (const int*)  d_in[1];
    const float* w1     = (const float*)d_in[2];
    const float* b1     = (const float*)d_in[3];
    const float* gamma1 = (const float*)d_in[4];
    const float* beta1  = (const float*)d_in[5];
    const float* w2     = (const float*)d_in[6];
    const float* gamma2 = (const float*)d_in[7];
    const float* beta2  = (const float*)d_in[8];
    float* out = (float*)d_out;

    float* gh;
    cudaGetSymbolAddress((void**)&gh, g_h);

    cudaFuncSetAttribute(conv_kernel<true>,
                         cudaFuncAttributeMaxDynamicSharedMemorySize, CONV_SMEM);
    cudaFuncSetAttribute(conv_kernel<false>,
                         cudaFuncAttributeMaxDynamicSharedMemorySize, CONV_SMEM);

    conv_kernel<true><<<CONVGRID, 128, CONV_SMEM>>>(data, ind, w1, b1, gh);
    midstats_kernel<<<MIDB, 256>>>();
    finalize_kernel<1><<<1, 32>>>(gamma1, beta1);
    bnapply_kernel<<<SGRID, 256>>>();                      // BN1+leaky on g_h
    conv_kernel<false><<<CONVGRID, 128, CONV_SMEM>>>(gh, ind, w2, nullptr, out);
    midstats_kernel<<<MIDB, 256>>>();
    finalize_kernel<2><<<1, 32>>>(gamma2, beta2);
    bnres_kernel<<<SGRID, 256>>>(data, out);
}

// round 11
// speedup vs baseline: 1.0145x; 1.0145x over previous
#include <cuda_runtime.h>
#include <cstddef>
#include <cstdint>

#define NPTS 1000000
#define KSZ 9
#define EPSBN 1e-5f
#define NF4 (NPTS * 16 / 4)
#define TILE 128
#define NTILES 7813               // ceil(1e6 / 128), last tile partial
#define GRIDC 148                 // persistent: 1 CTA per SM, 1 wave
#define SGRID 1184
#define SSTRIDE (SGRID * 256)
#define TILE_F4 (4 * KSZ * TILE)                    // 4608 float4 = 72 KB
#define CONV_SMEM (2 * TILE_F4 * 16 + KSZ * 256 * 4) // 147456 + 9216 = 156672

typedef unsigned long long ull;

// ---------------- scratch (device globals: no allocation) ----------------
__device__ float g_h[(size_t)NPTS * 16];           // conv1 raw output, 64 MB
__device__ float g_part[GRIDC * 32];               // per-block stats partials
__device__ __align__(16) float g_st1[32];          // BN1 scale[16], shift[16]
__device__ __align__(16) float g_st2[32];          // BN2 scale[16], shift[16]

// ---------------- f32x2 packed helpers ----------------
__device__ __forceinline__ void unpack2(ull v, float& lo, float& hi) {
    asm("mov.b64 {%0, %1}, %2;" : "=f"(lo), "=f"(hi) : "l"(v));
}
__device__ __forceinline__ ull pack2(float lo, float hi) {
    ull r; asm("mov.b64 %0, {%1, %2};" : "=l"(r) : "f"(lo), "f"(hi)); return r;
}
__device__ __forceinline__ ull fma2(ull a, ull b, ull c) {
    ull d; asm("fma.rn.f32x2 %0, %1, %2, %3;" : "=l"(d) : "l"(a), "l"(b), "l"(c)); return d;
}

// =====================================================================
// Tree-conv: persistent blocks (148), double-buffered cp.async pipeline,
// thread-per-point compute.
//  - tile = 128 points; stage tile t+148 while computing tile t
//  - A: thread reads ITS point's row once per j (4 LDS.128, conflict-free)
//  - W: all lanes read the same address -> smem broadcast (N=1)
//  - f32x2 over output-channel pairs; 8 independent accumulators (ILP)
//  - BN stats accumulated in registers across tiles, one reduce per block
// =====================================================================
template <bool BIAS>
__global__ void __launch_bounds__(128) conv_kernel(
    const float* __restrict__ src, const int* __restrict__ ind,
    const float* __restrict__ w, const float* __restrict__ bias,
    float* __restrict__ dst)
{
    extern __shared__ __align__(16) unsigned char dynsmem[];
    float4* sdat = reinterpret_cast<float4*>(dynsmem);                   // 2 buffers
    float*  wsm  = reinterpret_cast<float*>(dynsmem + 2 * TILE_F4 * 16); // 2304 floats

    const int tid = threadIdx.x;
    const int bid = blockIdx.x;

    // ---- stage weights: w[c][o][j] -> wsm[j][c][o] ----
    for (int i = tid; i < 16 * 16 * KSZ; i += 128) {
        int c = i / 144;
        int rem = i - c * 144;
        int o = rem / 9;
        int j = rem - o * 9;
        wsm[(j * 16 + c) * 16 + o] = w[i];
    }

    const float4* sp = reinterpret_cast<const float4*>(src);

    // stage one 128-point tile into buffer buf
    auto stage = [&](int tile, int buf) {
        const int base9 = tile * (TILE * KSZ);     // 1152 ints per tile
        float4* sb = sdat + buf * TILE_F4;
#pragma unroll
        for (int t = 0; t < 36; t++) {
            int i = tid + 128 * t;                 // 0..4607
            int u = i & 3;
            int jp = i >> 2;                       // 0..1151 == p*9 + j
            int idx = base9 + jp;
            if (idx >= NPTS * KSZ) idx = 0;        // clamp (last tile only)
            int row = __ldg(ind + idx);
            int p = jp / 9;
            int j = jp - p * 9;
            const float4* gsrc = sp + (size_t)row * 4 + u;
            uint32_t sa = (uint32_t)__cvta_generic_to_shared(&sb[(u * KSZ + j) * TILE + p]);
            asm volatile("cp.async.cg.shared.global [%0], [%1], 16;"
                         :: "r"(sa), "l"(gsrc));
        }
        asm volatile("cp.async.commit_group;");
    };

    float bsum[16], bsq[16];
#pragma unroll
    for (int c = 0; c < 16; c++) { bsum[c] = 0.f; bsq[c] = 0.f; }
    float4 bi0 = make_float4(0.f, 0.f, 0.f, 0.f), bi1 = bi0, bi2 = bi0, bi3 = bi0;
    if (BIAS) {
        bi0 = reinterpret_cast<const float4*>(bias)[0];
        bi1 = reinterpret_cast<const float4*>(bias)[1];
        bi2 = reinterpret_cast<const float4*>(bias)[2];
        bi3 = reinterpret_cast<const float4*>(bias)[3];
    }

    stage(bid, 0);
    int buf = 0;
    for (int tile = bid; tile < NTILES; tile += GRIDC) {
        const int nxt = tile + GRIDC;
        if (nxt < NTILES) {
            stage(nxt, buf ^ 1);
            asm volatile("cp.async.wait_group 1;" ::: "memory");
        } else {
            asm volatile("cp.async.wait_group 0;" ::: "memory");
        }
        __syncthreads();

        const float4* sb = sdat + buf * TILE_F4;
        ull acc[8];
#pragma unroll
        for (int i = 0; i < 8; i++) acc[i] = 0ull;

        for (int j = 0; j < KSZ; j++) {
            float4 A[4];
#pragma unroll
            for (int u = 0; u < 4; u++) A[u] = sb[(u * KSZ + j) * TILE + tid];
            const float* wj = wsm + j * 256;
#pragma unroll
            for (int c = 0; c < 16; c++) {
                const float v = (&A[c >> 2].x)[c & 3];
                const ull vp = pack2(v, v);
                const ulonglong2* wv = reinterpret_cast<const ulonglong2*>(wj + c * 16);
                ulonglong2 w0 = wv[0];                 // broadcast addresses
                ulonglong2 w1 = wv[1];
                acc[0] = fma2(vp, w0.x, acc[0]);
                acc[1] = fma2(vp, w0.y, acc[1]);
                acc[2] = fma2(vp, w1.x, acc[2]);
                acc[3] = fma2(vp, w1.y, acc[3]);
                ulonglong2 w2 = wv[2];
                ulonglong2 w3 = wv[3];
                acc[4] = fma2(vp, w2.x, acc[4]);
                acc[5] = fma2(vp, w2.y, acc[5]);
                acc[6] = fma2(vp, w3.x, acc[6]);
                acc[7] = fma2(vp, w3.y, acc[7]);
            }
        }

        const int pt = tile * TILE + tid;
        if (pt < NPTS) {
            float o[16];
#pragma unroll
            for (int i = 0; i < 8; i++) unpack2(acc[i], o[2 * i], o[2 * i + 1]);
            if (BIAS) {
                o[0] += bi0.x;  o[1] += bi0.y;  o[2] += bi0.z;  o[3] += bi0.w;
                o[4] += bi1.x;  o[5] += bi1.y;  o[6] += bi1.z;  o[7] += bi1.w;
                o[8] += bi2.x;  o[9] += bi2.y;  o[10] += bi2.z; o[11] += bi2.w;
                o[12] += bi3.x; o[13] += bi3.y; o[14] += bi3.z; o[15] += bi3.w;
            }
            float4* op = reinterpret_cast<float4*>(dst) + (size_t)pt * 4;
            op[0] = make_float4(o[0], o[1], o[2], o[3]);
            op[1] = make_float4(o[4], o[5], o[6], o[7]);
            op[2] = make_float4(o[8], o[9], o[10], o[11]);
            op[3] = make_float4(o[12], o[13], o[14], o[15]);
#pragma unroll
            for (int c = 0; c < 16; c++) {
                bsum[c] += o[c];
                bsq[c] += o[c] * o[c];
            }
        }
        __syncthreads();   // buffer free before next stage overwrites it
        buf ^= 1;
    }

    // ---- per-block stats reduce (reuse sdat smem; deterministic) ----
    float* red = reinterpret_cast<float*>(dynsmem);    // 128 * 32 floats
#pragma unroll
    for (int c = 0; c < 16; c++) {
        red[tid * 32 + c] = bsum[c];
        red[tid * 32 + 16 + c] = bsq[c];
    }
    __syncthreads();
    if (tid < 32) {
        float t = 0.f;
        for (int r = 0; r < 128; r++) t += red[r * 32 + tid];
        g_part[bid * 32 + tid] = t;
    }
}

// ---------------- finalize: GRIDC partials -> BN scale/shift ----------------
template <int S>
__global__ void finalize_kernel(const float* __restrict__ gamma,
                                const float* __restrict__ beta)
{
    const int tid = threadIdx.x;   // 128 threads
    const int v = tid & 31;
    const int part = tid >> 5;     // 4 chunks
    float loc = 0.f;
    for (int r = part; r < GRIDC; r += 4) loc += g_part[r * 32 + v];
    __shared__ float sm[128];
    sm[tid] = loc;
    __syncthreads();
    if (tid < 32) sm[tid] = sm[tid] + sm[tid + 32] + sm[tid + 64] + sm[tid + 96];
    __syncthreads();
    if (tid < 16) {
        const float inv_n = 1.0f / (float)NPTS;
        float mean = sm[tid] * inv_n;
        float var = sm[16 + tid] * inv_n - mean * mean;
        float rstd = rsqrtf(var + EPSBN);
        float sc = gamma[tid] * rstd;
        float sh = beta[tid] - mean * sc;
        float* st = (S == 1) ? g_st1 : g_st2;
        st[tid] = sc;
        st[16 + tid] = sh;
    }
}

// ---------------- BN1 + leaky applied in place on g_h ----------------
__global__ __launch_bounds__(256) void bnapply_kernel()
{
    const int tid = threadIdx.x;
    const int idx = blockIdx.x * 256 + tid;
    const int g = tid & 3;
    float4 sc = reinterpret_cast<const float4*>(g_st1)[g];
    float4 sh = reinterpret_cast<const float4*>(g_st1 + 16)[g];
    float4* hh = reinterpret_cast<float4*>(g_h);
    for (int i = idx; i < NF4; i += SSTRIDE) {
        float4 v = hh[i];
        v.x = fmaf(v.x, sc.x, sh.x); v.x = fmaxf(v.x, 0.2f * v.x);
        v.y = fmaf(v.y, sc.y, sh.y); v.y = fmaxf(v.y, 0.2f * v.y);
        v.z = fmaf(v.z, sc.z, sh.z); v.z = fmaxf(v.z, 0.2f * v.z);
        v.w = fmaf(v.w, sc.w, sh.w); v.w = fmaxf(v.w, 0.2f * v.w);
        hh[i] = v;
    }
}

// ---------- epilogue: out = leaky(BN2(raw2) + data), in place on d_out ----------
__global__ __launch_bounds__(256) void bnres_kernel(
    const float* __restrict__ data, float* __restrict__ out)
{
    const int tid = threadIdx.x;
    const int idx = blockIdx.x * 256 + tid;
    const int g = tid & 3;
    float4 sc = reinterpret_cast<const float4*>(g_st2)[g];
    float4 sh = reinterpret_cast<const float4*>(g_st2 + 16)[g];
    const float4* dd = reinterpret_cast<const float4*>(data);
    float4* oo = reinterpret_cast<float4*>(out);
    for (int i = idx; i < NF4; i += SSTRIDE) {
        float4 r = oo[i];
        float4 d = dd[i];
        float4 y;
        y.x = fmaf(r.x, sc.x, sh.x) + d.x;
        y.y = fmaf(r.y, sc.y, sh.y) + d.y;
        y.z = fmaf(r.z, sc.z, sh.z) + d.z;
        y.w = fmaf(r.w, sc.w, sh.w) + d.w;
        y.x = fmaxf(y.x, 0.2f * y.x);
        y.y = fmaxf(y.y, 0.2f * y.y);
        y.z = fmaxf(y.z, 0.2f * y.z);
        y.w = fmaxf(y.w, 0.2f * y.w);
        oo[i] = y;
    }
}

extern "C" void kernel_launch(void* const* d_in, const int* in_sizes, int n_in,
                              void* d_out, int out_size)
{
    const float* data   = (const float*)d_in[0];
    const int*   ind    = (const int*)  d_in[1];
    const float* w1     = (const float*)d_in[2];
    const float* b1     = (const float*)d_in[3];
    const float* gamma1 = (const float*)d_in[4];
    const float* beta1  = (const float*)d_in[5];
    const float* w2     = (const float*)d_in[6];
    const float* gamma2 = (const float*)d_in[7];
    const float* beta2  = (const float*)d_in[8];
    float* out = (float*)d_out;

    float* gh;
    cudaGetSymbolAddress((void**)&gh, g_h);

    cudaFuncSetAttribute(conv_kernel<true>,
                         cudaFuncAttributeMaxDynamicSharedMemorySize, CONV_SMEM);
    cudaFuncSetAttribute(conv_kernel<false>,
                         cudaFuncAttributeMaxDynamicSharedMemorySize, CONV_SMEM);

    conv_kernel<true><<<GRIDC, 128, CONV_SMEM>>>(data, ind, w1, b1, gh);
    finalize_kernel<1><<<1, 128>>>(gamma1, beta1);
    bnapply_kernel<<<SGRID, 256>>>();                      // BN1+leaky on g_h
    conv_kernel<false><<<GRIDC, 128, CONV_SMEM>>>(gh, ind, w2, nullptr, out);
    finalize_kernel<2><<<1, 128>>>(gamma2, beta2);
    bnres_kernel<<<SGRID, 256>>>(data, out);
}

// round 13
// speedup vs baseline: 1.6905x; 1.6664x over previous
#include <cuda_runtime.h>
#include <cstddef>
#include <cstdint>

#define NPTS 1000000
#define KSZ 9
#define EPSBN 1e-5f
#define NF4 (NPTS * 16 / 4)
#define CONVGRID 7813             // 128 points per block (last block partial)
#define MIDB 64
#define RPB ((CONVGRID + MIDB - 1) / MIDB)
#define SGRID 1184
#define SSTRIDE (SGRID * 256)

typedef unsigned long long ull;

// ---------------- scratch (device globals: no allocation) ----------------
__device__ float g_h[(size_t)NPTS * 16];           // conv1 raw output, 64 MB
__device__ float4 g_part4[CONVGRID * 8];           // per-block stats partials
__device__ float g_mid[MIDB * 32];
__device__ __align__(16) float g_st1[32];          // BN1 scale[16], shift[16]
__device__ __align__(16) float g_st2[32];          // BN2 scale[16], shift[16]

// ---------------- f32x2 packed helpers ----------------
__device__ __forceinline__ ull pack2(float lo, float hi) {
    ull r; asm("mov.b64 %0, {%1, %2};" : "=l"(r) : "f"(lo), "f"(hi)); return r;
}
__device__ __forceinline__ void unpack2(ull v, float& lo, float& hi) {
    asm("mov.b64 {%0, %1}, %2;" : "=f"(lo), "=f"(hi) : "l"(v));
}
__device__ __forceinline__ ull fma2(ull a, ull b, ull c) {
    ull d; asm("fma.rn.f32x2 %0, %1, %2, %3;" : "=l"(d) : "l"(a), "l"(b), "l"(c)); return d;
}
__device__ __forceinline__ ull add2(ull a, ull b) {
    ull d; asm("add.rn.f32x2 %0, %1, %2;" : "=l"(d) : "l"(a), "l"(b)); return d;
}

#define BNAPP(v, s, h) { v = fmaf(v, s, h); v = fmaxf(v, 0.2f * v); }

// =====================================================================
// Fused tree-conv, software-pipelined gather.
//  - 4 lanes per point-column (lane g owns input channels 4g..4g+3)
//  - 2 points per thread; warp covers 16 consecutive points
//  - pipeline: ind fetched 2 iterations ahead, row data 1 ahead
//    (load-use distance ~1 full j iteration; 2 CTAs/SM via launch bounds)
//  - weights: f32x2 output-channel pairs, bank-skewed smem, not duplicated
//  - per-block BN stats (sum, sumsq per channel) fused at the end
// =====================================================================
template <bool BN, bool BIAS>
__global__ void __launch_bounds__(256, 2) conv_kernel(
    const float* __restrict__ src, const int* __restrict__ ind,
    const float* __restrict__ w, const float* __restrict__ bias,
    float* __restrict__ dst)
{
    // ws[g][j][cc][o]: g-stride 580 floats (580 mod 32 = 4 -> 4 group
    // addresses on disjoint banks). Reused for stats reduction (needs 2048).
    __shared__ __align__(16) float ws[4 * 580];
    const int tid = threadIdx.x;
    const int g = tid & 3;
    const int G = tid >> 2;

    for (int i = tid; i < 16 * 16 * KSZ; i += 256) {
        int c = i / 144;
        int rem = i - c * 144;
        int o = rem / 9;
        int j = rem - o * 9;
        ws[(c >> 2) * 580 + j * 64 + (c & 3) * 16 + o] = w[i];
    }
    __syncthreads();

    float4 bsc, bsh;
    if (BN) {
        bsc = reinterpret_cast<const float4*>(g_st1)[g];
        bsh = reinterpret_cast<const float4*>(g_st1 + 16)[g];
    }

    const int pbase = blockIdx.x * 128;
    const int n0 = pbase + G;            // always < NPTS (max 999,999)
    const int n1 = n0 + 64;
    const bool v1 = n1 < NPTS;
    const int ib0 = n0 * KSZ;
    const int ib1 = v1 ? n1 * KSZ : 0;   // clamp: row data unused for invalid pt

    ull acc[2][8];
#pragma unroll
    for (int k = 0; k < 2; k++)
#pragma unroll
        for (int p = 0; p < 8; p++) acc[k][p] = 0ull;

    const float4* sp = reinterpret_cast<const float4*>(src);
    const float* wg = ws + g * 580;

    // ---- pipeline prologue: ind(j0), ind(j1), data(j0) ----
    int rn0 = __ldg(ind + ib0);          // ind for j = 0
    int rn1 = __ldg(ind + ib1);
    float4 ac0 = __ldg(sp + (size_t)rn0 * 4 + g);
    float4 ac1 = __ldg(sp + (size_t)rn1 * 4 + g);
    rn0 = __ldg(ind + ib0 + 1);          // ind for j = 1
    rn1 = __ldg(ind + ib1 + 1);

#pragma unroll
    for (int j = 0; j < KSZ; j++) {
        float4 an0, an1;
        if (j < KSZ - 1) {
            // issue next row data (ind already resident), then ind for j+2
            an0 = __ldg(sp + (size_t)rn0 * 4 + g);
            an1 = __ldg(sp + (size_t)rn1 * 4 + g);
            const int j2 = (j + 2 <= KSZ - 1) ? j + 2 : KSZ - 1;
            rn0 = __ldg(ind + ib0 + j2);
            rn1 = __ldg(ind + ib1 + j2);
        }

        float4 a0 = ac0, a1 = ac1;
        if (BN) {
            BNAPP(a0.x, bsc.x, bsh.x); BNAPP(a0.y, bsc.y, bsh.y);
            BNAPP(a0.z, bsc.z, bsh.z); BNAPP(a0.w, bsc.w, bsh.w);
            BNAPP(a1.x, bsc.x, bsh.x); BNAPP(a1.y, bsc.y, bsh.y);
            BNAPP(a1.z, bsc.z, bsh.z); BNAPP(a1.w, bsc.w, bsh.w);
        }

        const ulonglong2* wj = reinterpret_cast<const ulonglong2*>(wg + j * 64);
#pragma unroll
        for (int cc = 0; cc < 4; cc++) {
            ulonglong2 w0 = wj[cc * 4 + 0];
            ulonglong2 w1 = wj[cc * 4 + 1];
            ulonglong2 w2 = wj[cc * 4 + 2];
            ulonglong2 w3 = wj[cc * 4 + 3];
            {
                const float v = (cc == 0) ? a0.x : (cc == 1) ? a0.y
                              : (cc == 2) ? a0.z : a0.w;
                const ull v2 = pack2(v, v);
                acc[0][0] = fma2(v2, w0.x, acc[0][0]);
                acc[0][1] = fma2(v2, w0.y, acc[0][1]);
                acc[0][2] = fma2(v2, w1.x, acc[0][2]);
                acc[0][3] = fma2(v2, w1.y, acc[0][3]);
                acc[0][4] = fma2(v2, w2.x, acc[0][4]);
                acc[0][5] = fma2(v2, w2.y, acc[0][5]);
                acc[0][6] = fma2(v2, w3.x, acc[0][6]);
                acc[0][7] = fma2(v2, w3.y, acc[0][7]);
            }
            {
                const float v = (cc == 0) ? a1.x : (cc == 1) ? a1.y
                              : (cc == 2) ? a1.z : a1.w;
                const ull v2 = pack2(v, v);
                acc[1][0] = fma2(v2, w0.x, acc[1][0]);
                acc[1][1] = fma2(v2, w0.y, acc[1][1]);
                acc[1][2] = fma2(v2, w1.x, acc[1][2]);
                acc[1][3] = fma2(v2, w1.y, acc[1][3]);
                acc[1][4] = fma2(v2, w2.x, acc[1][4]);
                acc[1][5] = fma2(v2, w2.y, acc[1][5]);
                acc[1][6] = fma2(v2, w3.x, acc[1][6]);
                acc[1][7] = fma2(v2, w3.y, acc[1][7]);
            }
        }
        ac0 = an0; ac1 = an1;
    }

    // reduce-scatter per point; accumulate block stats
    float4 s4 = make_float4(0.f, 0.f, 0.f, 0.f);
    float4 q4 = make_float4(0.f, 0.f, 0.f, 0.f);
    float4 b4;
    if (BIAS) b4 = reinterpret_cast<const float4*>(bias)[g];

#pragma unroll
    for (int k = 0; k < 2; k++) {
        ull h4[4];
#pragma unroll
        for (int i = 0; i < 4; i++) {
            ull aa = acc[k][i], bb = acc[k][i + 4];
            ull mine = (g & 2) ? aa : bb;
            ull oth = __shfl_xor_sync(0xffffffffu, mine, 2);
            h4[i] = add2((g & 2) ? bb : aa, oth);
        }
        ull q2[2];
#pragma unroll
        for (int i = 0; i < 2; i++) {
            ull aa = h4[i], bb = h4[i + 2];
            ull mine = (g & 1) ? aa : bb;
            ull oth = __shfl_xor_sync(0xffffffffu, mine, 1);
            q2[i] = add2((g & 1) ? bb : aa, oth);
        }
        float o0, o1, o2, o3;
        unpack2(q2[0], o0, o1);
        unpack2(q2[1], o2, o3);
        if (BIAS) { o0 += b4.x; o1 += b4.y; o2 += b4.z; o3 += b4.w; }
        const int np = (k == 0) ? n0 : n1;
        const bool vv = (k == 0) ? true : v1;
        if (vv) {
            reinterpret_cast<float4*>(dst)[(size_t)np * 4 + g] =
                make_float4(o0, o1, o2, o3);
            s4.x += o0; s4.y += o1; s4.z += o2; s4.w += o3;
            q4.x += o0 * o0; q4.y += o1 * o1; q4.z += o2 * o2; q4.w += o3 * o3;
        }
    }

    // ---- fused per-block BN stats (deterministic), reuse weight smem ----
    __syncthreads();
    float4* s1 = reinterpret_cast<float4*>(ws);        // 256 float4
    float4* s2 = s1 + 256;
    s1[tid] = s4; s2[tid] = q4;
    __syncthreads();
#pragma unroll
    for (int off = 128; off >= 4; off >>= 1) {
        if (tid < off) {
            float4 a = s1[tid], b = s1[tid + off];
            a.x += b.x; a.y += b.y; a.z += b.z; a.w += b.w; s1[tid] = a;
            float4 c = s2[tid], d = s2[tid + off];
            c.x += d.x; c.y += d.y; c.z += d.z; c.w += d.w; s2[tid] = c;
        }
        __syncthreads();
    }
    if (tid < 4) {
        g_part4[blockIdx.x * 8 + tid] = s1[tid];
        g_part4[blockIdx.x * 8 + 4 + tid] = s2[tid];
    }
}

// ---------------- mid-stage stats reduction: CONVGRID -> 64 partials ----------------
__global__ __launch_bounds__(256) void midstats_kernel()
{
    const float* part = reinterpret_cast<const float*>(g_part4);
    const int tid = threadIdx.x;
    const int v = tid & 31;
    const int lane = tid >> 5;
    const int r0 = blockIdx.x * RPB;
    const int rend = min(r0 + RPB, CONVGRID);
    float loc = 0.f;
    for (int r = r0 + lane; r < rend; r += 8) loc += part[r * 32 + v];
    __shared__ float sm[256];
    sm[tid] = loc;
    __syncthreads();
    if (tid < 32) {
        float t = 0.f;
#pragma unroll
        for (int k = 0; k < 8; k++) t += sm[tid + k * 32];
        g_mid[blockIdx.x * 32 + tid] = t;
    }
}

// ---------------- finalize: 64 partials -> BN scale/shift ----------------
template <int S>
__global__ void finalize_kernel(const float* __restrict__ gamma,
                                const float* __restrict__ beta)
{
    const int tid = threadIdx.x;   // 32 threads
    __shared__ float sm[32];
    float t = 0.f;
    for (int r = 0; r < MIDB; r++) t += g_mid[r * 32 + tid];
    sm[tid] = t;
    __syncthreads();
    if (tid < 16) {
        const float inv_n = 1.0f / (float)NPTS;
        float mean = sm[tid] * inv_n;
        float var = sm[16 + tid] * inv_n - mean * mean;
        float rstd = rsqrtf(var + EPSBN);
        float sc = gamma[tid] * rstd;
        float sh = beta[tid] - mean * sc;
        float* st = (S == 1) ? g_st1 : g_st2;
        st[tid] = sc;
        st[16 + tid] = sh;
    }
}

// ---------- epilogue: out = leaky(BN2(raw2) + data), in place on d_out ----------
__global__ __launch_bounds__(256) void bnres_kernel(
    const float* __restrict__ data, float* __restrict__ out)
{
    const int tid = threadIdx.x;
    const int idx = blockIdx.x * 256 + tid;
    const int g = tid & 3;
    float4 sc = reinterpret_cast<const float4*>(g_st2)[g];
    float4 sh = reinterpret_cast<const float4*>(g_st2 + 16)[g];
    const float4* dd = reinterpret_cast<const float4*>(data);
    float4* oo = reinterpret_cast<float4*>(out);
    for (int i = idx; i < NF4; i += SSTRIDE) {
        float4 r = oo[i];
        float4 d = dd[i];
        float4 y;
        y.x = fmaf(r.x, sc.x, sh.x) + d.x;
        y.y = fmaf(r.y, sc.y, sh.y) + d.y;
        y.z = fmaf(r.z, sc.z, sh.z) + d.z;
        y.w = fmaf(r.w, sc.w, sh.w) + d.w;
        y.x = fmaxf(y.x, 0.2f * y.x);
        y.y = fmaxf(y.y, 0.2f * y.y);
        y.z = fmaxf(y.z, 0.2f * y.z);
        y.w = fmaxf(y.w, 0.2f * y.w);
        oo[i] = y;
    }
}

extern "C" void kernel_launch(void* const* d_in, const int* in_sizes, int n_in,
                              void* d_out, int out_size)
{
    const float* data   = (const float*)d_in[0];
    const int*   ind    = (const int*)  d_in[1];
    const float* w1     = (const float*)d_in[2];
    const float* b1     = (const float*)d_in[3];
    const float* gamma1 = (const float*)d_in[4];
    const float* beta1  = (const float*)d_in[5];
    const float* w2     = (const float*)d_in[6];
    const float* gamma2 = (const float*)d_in[7];
    const float* beta2  = (const float*)d_in[8];
    float* out = (float*)d_out;

    float* gh;
    cudaGetSymbolAddress((void**)&gh, g_h);

    conv_kernel<false, true><<<CONVGRID, 256>>>(data, ind, w1, b1, gh);
    midstats_kernel<<<MIDB, 256>>>();
    finalize_kernel<1><<<1, 32>>>(gamma1, beta1);
    conv_kernel<true, false><<<CONVGRID, 256>>>(gh, ind, w2, nullptr, out);
    midstats_kernel<<<MIDB, 256>>>();
    finalize_kernel<2><<<1, 32>>>(gamma2, beta2);
    bnres_kernel<<<SGRID, 256>>>(data, out);
}